// round 8
// baseline (speedup 1.0000x reference)
#include <cuda_runtime.h>
#include <cstdint>
#include <math.h>

// Problem dims
#define BB   128
#define TT   1024
#define II   256
#define HH   512
#define G4H  2048

// Phase 2 config
#define P2_GRID    128
#define P2_THREADS 512
#define KPT  256       // total k-pairs (512 k)
#define KPC  32        // k-pairs per chunk
#define NCH  8
#define NBUF 4
#define AST  130       // activation row stride (ull)
#define WST  18        // weight row stride (ull)

// Phase 1 config
#define P1_THREADS 512
#define P1_KPCH 16     // k-pairs per weight chunk
#define P1_NCH  (II / 2 / P1_KPCH)   // 8 chunks
#define XS_STRIDE  130

typedef unsigned long long ull;

__device__ float g_xg[(size_t)TT * G4H * BB];  // [t][prow][b] x-gates + biases
__device__ ull   g_hT_pk[2][KPT * BB];         // [buf][kp][b] h k-pair packed
__device__ unsigned g_bar_count;
__device__ unsigned g_bar_gen;

// ---------- packed fp32 helpers ----------
__device__ __forceinline__ void fma2(ull &d, ull a, ull b) {
    asm("fma.rn.f32x2 %0, %1, %2, %0;" : "+l"(d) : "l"(a), "l"(b));
}
__device__ __forceinline__ ull pack2(float lo, float hi) {
    ull r; asm("mov.b64 %0, {%1, %2};" : "=l"(r) : "f"(lo), "f"(hi)); return r;
}
__device__ __forceinline__ void unpack2(float &lo, float &hi, ull v) {
    asm("mov.b64 {%0, %1}, %2;" : "=f"(lo), "=f"(hi) : "l"(v));
}
// ---------- cp.async ----------
__device__ __forceinline__ void cp_async16(void* dst_smem, const void* src) {
    unsigned d = (unsigned)__cvta_generic_to_shared(dst_smem);
    asm volatile("cp.async.cg.shared.global [%0], [%1], 16;" :: "r"(d), "l"(src));
}
__device__ __forceinline__ void cp_commit() { asm volatile("cp.async.commit_group;"); }
template<int N> __device__ __forceinline__ void cp_wait() {
    asm volatile("cp.async.wait_group %0;" :: "n"(N));
}

__device__ __forceinline__ float sigf(float x) { return 1.0f / (1.0f + expf(-x)); }

__device__ __forceinline__ int prow_to_n(int prow) {
    int c2 = prow >> 4, r = prow & 15;
    return (r & 3) * HH + c2 * 4 + (r >> 2);
}

// ---------- grid-wide barrier (monotonic count) ----------
__device__ __forceinline__ void grid_barrier(unsigned target) {
    __syncthreads();
    __threadfence();
    if (threadIdx.x == 0) {
        unsigned a = atomicAdd(&g_bar_count, 1u) + 1u;
        if (a == (unsigned)P2_GRID * target) {
            __threadfence();
            atomicAdd(&g_bar_gen, 1u);
        } else {
            while (*(volatile unsigned*)&g_bar_gen < target) { }
        }
        __threadfence();
    }
    __syncthreads();
}

// ============================================================================
// Phase 1: xg[t][prow][b] = x.W_ih^T + b_ih + b_hh
// Weights staged in smem via triple-buffered cp.async (16-kp chunks) — the
// inner loop is pure LDS + FFMA2, no LDG latency in the dependence chain.
// ============================================================================
__global__ void __launch_bounds__(P1_THREADS, 1) xgate_kernel(
    const float* __restrict__ x, const float* __restrict__ W_ih,
    const float* __restrict__ b_ih, const float* __restrict__ b_hh)
{
    extern __shared__ char smem[];
    ull*   xs2   = (ull*)smem;                       // [128 b][130 kp]
    float* s_out = (float*)smem;                     // reuse after compute
    ull*   wbuf  = (ull*)(smem + BB * XS_STRIDE * 8);// [3][128 row][18]

    const int tid = threadIdx.x;
    const int gy  = blockIdx.x;
    const int t   = blockIdx.y;

    if (gy == 0 && t == 0 && tid == 0) { g_bar_count = 0u; g_bar_gen = 0u; }

    // Stage x_t transposed + k-pair packed
    for (int e = tid; e < BB * (II / 4); e += P1_THREADS) {
        int b = e >> 6, v = e & 63;
        float4 f = *(const float4*)(x + ((size_t)b * TT + t) * II + 4 * v);
        ulonglong2 u;
        u.x = pack2(f.x, f.y);
        u.y = pack2(f.z, f.w);
        *(ulonglong2*)&xs2[b * XS_STRIDE + 2 * v] = u;
    }

    // Weight chunk prefetch (c -> wbuf[c%3]); 1024 cp16 per chunk, 2/thread
    auto load_w = [&](int c) {
        ull* dst = wbuf + (c % 3) * (128 * WST);
        #pragma unroll
        for (int j = 0; j < 2; j++) {
            int u = tid + j * P1_THREADS;
            int row = u >> 3, kq = u & 7;
            int n = prow_to_n(gy * 128 + row);
            cp_async16(dst + row * WST + kq * 2,
                       W_ih + (size_t)n * II + c * (P1_KPCH * 2) + kq * 4);
        }
    };
    load_w(0); cp_commit();
    load_w(1); cp_commit();
    __syncthreads();   // xs2 ready

    const int rs   = tid >> 3;
    const int boct = tid & 7;
    const int p0   = gy * 128 + rs * 2;
    const int n0 = prow_to_n(p0), n1 = prow_to_n(p0 + 1);
    const float bias0 = b_ih[n0] + b_hh[n0];
    const float bias1 = b_ih[n1] + b_hh[n1];

    ull acc0[16], acc1[16];
    #pragma unroll
    for (int bb = 0; bb < 16; bb++) {
        acc0[bb] = pack2(bias0, 0.f);
        acc1[bb] = pack2(bias1, 0.f);
    }

    #pragma unroll 1
    for (int c = 0; c < P1_NCH; c++) {
        if (c == P1_NCH - 1) cp_wait<1>(); else cp_wait<1>();
        __syncthreads();                 // chunk c landed; compute c-1 done
        if (c + 2 < P1_NCH) { load_w(c + 2); cp_commit(); }
        else                { cp_commit(); }   // empty: uniform accounting

        const ull* wb = wbuf + (c % 3) * (128 * WST);
        const ull* w0p = wb + (rs * 2) * WST;
        const ull* w1p = wb + (rs * 2 + 1) * WST;
        #pragma unroll 4
        for (int kpl = 0; kpl < P1_KPCH; kpl++) {
            ull w0 = w0p[kpl];
            ull w1 = w1p[kpl];
            const ull* ab = xs2 + c * P1_KPCH + kpl;
            #pragma unroll
            for (int bb = 0; bb < 16; bb++) {
                ull a = ab[(boct + 8 * bb) * XS_STRIDE];
                fma2(acc0[bb], a, w0);
                fma2(acc1[bb], a, w1);
            }
        }
    }
    __syncthreads();  // all xs2/wbuf reads done before s_out overwrite

    #pragma unroll
    for (int bb = 0; bb < 16; bb++) {
        float lo, hi;
        unpack2(lo, hi, acc0[bb]);
        s_out[(rs * 2 + 0) * 129 + boct + 8 * bb] = lo + hi;
        unpack2(lo, hi, acc1[bb]);
        s_out[(rs * 2 + 1) * 129 + boct + 8 * bb] = lo + hi;
    }
    __syncthreads();

    float* dst = g_xg + ((size_t)t * G4H + gy * 128) * BB;
    for (int e = tid; e < 128 * 128; e += P1_THREADS) {
        int row = e >> 7, b = e & 127;
        dst[e] = s_out[row * 129 + b];
    }
}

// ---------- phase-2 chunk loader ----------
__device__ __forceinline__ void load_chunk(ull* As, int ci,
                                           const ull* __restrict__ hsrc, int tid) {
    ull* dst = As + (ci & 3) * (KPC * AST);
    const ull* src = hsrc + ci * KPC * BB;
    #pragma unroll
    for (int j = 0; j < 4; j++) {
        int u   = tid + j * P2_THREADS;   // 0..2047 16B units
        int kpl = u >> 6;
        int bu  = u & 63;
        cp_async16(dst + kpl * AST + bu * 2, src + kpl * BB + bu * 2);
    }
}

// ============================================================================
// Phase 2: persistent recurrence. 512 threads (4 warps/SMSP).
// lane: kps = l&7 (K slice), rg = (l>>3)&1 (row group), bh = l>>4.
// Thread tile: 8 gate-rows (rg) x 4 batches (bg = w*2+bh), acc[8][4].
// Selective shfl reduction -> each thread owns ONE (h-col, batch).
// ============================================================================
__global__ void __launch_bounds__(P2_THREADS, 1) lstm_kernel(
    const float* __restrict__ W_hh, float* __restrict__ out)
{
    extern __shared__ char smem[];
    ull*   wsm = (ull*)smem;                      // [256 kp][18]
    ull*   As  = wsm + KPT * WST;                 // [4][32][130]
    float* xgs = (float*)(As + NBUF * KPC * AST); // [2][16][128]

    const int tid = threadIdx.x;
    const int w   = tid >> 5, l = tid & 31;
    const int kps = l & 7;
    const int rg  = (l >> 3) & 1;
    const int bg  = w * 2 + (l >> 4);     // 0..31: batches bg*4..+3
    const int cta = blockIdx.x;
    // post-reduction ownership:
    const int fhcl = rg * 2 + (kps >> 2);            // local h-col 0..3
    const int fb   = bg * 4 + ((kps >> 1) & 1) * 2 + (kps & 1);  // batch

    // Weights once: wsm[kp*WST + r] = (W_hh[n][2kp], W_hh[n][2kp+1])
    for (int idx = tid; idx < KPT * 16; idx += P2_THREADS) {
        int kp = idx >> 4, r = idx & 15;
        int n = (r & 3) * HH + cta * 4 + (r >> 2);
        wsm[kp * WST + r] = ((const ull*)W_hh)[(size_t)n * (HH / 2) + kp];
    }
    // Zero h buf0 own rows (2 kp rows x 128 b)
    if (tid < 256)
        g_hT_pk[0][(cta * 2 + (tid >> 7)) * BB + (tid & 127)] = 0ull;
    // Prefetch xg(0)
    {
        const float* src = g_xg + ((size_t)cta * 16) * BB;
        cp_async16(xgs + tid * 4, src + tid * 4);
        cp_commit();
    }

    float cc = 0.f;   // cell state for (fhcl, fb)
    unsigned gen = 0;
    grid_barrier(++gen);

    for (int t = 0; t < TT; t++) {
        const ull* hsrc = g_hT_pk[t & 1];

        load_chunk(As, 0, hsrc, tid); cp_commit();
        load_chunk(As, 1, hsrc, tid); cp_commit();

        ull acc[8][4];
        #pragma unroll
        for (int ri = 0; ri < 8; ri++)
            #pragma unroll
            for (int bi = 0; bi < 4; bi++) acc[ri][bi] = 0ull;

        #pragma unroll 1
        for (int ci = 0; ci < NCH; ci++) {
            if (ci < NCH - 2) {
                load_chunk(As, ci + 2, hsrc, tid);
                cp_commit();
            } else if (ci == NCH - 2) {
                if (t + 1 < TT) {
                    const float* src = g_xg + ((size_t)(t + 1) * G4H + cta * 16) * BB;
                    cp_async16(xgs + ((t + 1) & 1) * 2048 + tid * 4, src + tid * 4);
                }
                cp_commit();
            }
            if (ci == NCH - 1) cp_wait<1>(); else cp_wait<2>();
            __syncthreads();

            const ull* Ab = As + (ci & 3) * (KPC * AST);
            #pragma unroll
            for (int jj = 0; jj < 4; jj++) {
                const int kpl = jj * 8 + kps;
                const ull* ap = Ab + kpl * AST + bg * 4;
                const ull* wp = wsm + (ci * KPC + kpl) * WST + rg * 8;
                ulonglong2 a01 = *(const ulonglong2*)(ap + 0);
                ulonglong2 a23 = *(const ulonglong2*)(ap + 2);
                ulonglong2 w01 = *(const ulonglong2*)(wp + 0);
                ulonglong2 w23 = *(const ulonglong2*)(wp + 2);
                ulonglong2 w45 = *(const ulonglong2*)(wp + 4);
                ulonglong2 w67 = *(const ulonglong2*)(wp + 6);
                ull av[4] = {a01.x, a01.y, a23.x, a23.y};
                ull wv[8] = {w01.x, w01.y, w23.x, w23.y, w45.x, w45.y, w67.x, w67.y};
                #pragma unroll
                for (int ri = 0; ri < 8; ri++)
                    #pragma unroll
                    for (int bi = 0; bi < 4; bi++)
                        fma2(acc[ri][bi], av[bi], wv[ri]);
            }
        }

        // ---- fold k-parity, then selective shfl reduction over kps ----
        float v[8][4];
        #pragma unroll
        for (int ri = 0; ri < 8; ri++)
            #pragma unroll
            for (int bi = 0; bi < 4; bi++) {
                float lo, hi; unpack2(lo, hi, acc[ri][bi]);
                v[ri][bi] = lo + hi;
            }
        const bool s0 = kps & 1, s1 = kps & 2, s2 = kps & 4;
        float u2[8][2];
        #pragma unroll
        for (int ri = 0; ri < 8; ri++)
            #pragma unroll
            for (int bp = 0; bp < 2; bp++) {
                float keep = s0 ? v[ri][2 * bp + 1] : v[ri][2 * bp];
                float send = s0 ? v[ri][2 * bp]     : v[ri][2 * bp + 1];
                u2[ri][bp] = keep + __shfl_xor_sync(0xffffffffu, send, 1);
            }
        float z[8];
        #pragma unroll
        for (int ri = 0; ri < 8; ri++) {
            float keep = s1 ? u2[ri][1] : u2[ri][0];
            float send = s1 ? u2[ri][0] : u2[ri][1];
            z[ri] = keep + __shfl_xor_sync(0xffffffffu, send, 2);
        }
        float g4[4];
        #pragma unroll
        for (int q = 0; q < 4; q++) {
            float keep = s2 ? z[4 + q] : z[q];
            float send = s2 ? z[q]     : z[4 + q];
            g4[q] = keep + __shfl_xor_sync(0xffffffffu, send, 4);
        }
        // g4[gate] = recurrent sum for (h-col cta*4+fhcl, batch fb)

        const float* xc = xgs + (t & 1) * 2048 + fhcl * 4 * BB + fb;
        float ig = sigf (g4[0] + xc[0 * BB]);
        float fg = sigf (g4[1] + xc[1 * BB]);
        float gg = tanhf(g4[2] + xc[2 * BB]);
        float og = sigf (g4[3] + xc[3 * BB]);
        cc = fg * cc + ig * gg;
        float hv = og * tanhf(cc);

        if (t < TT - 1) {
            // scatter into k-pair-packed h: float element (kp row, b, parity)
            ((float*)g_hT_pk[(t + 1) & 1])
                [(((size_t)(cta * 2 + rg)) * BB + fb) * 2 + (kps >> 2)] = hv;
            grid_barrier(++gen);
        } else {
            out[(size_t)fb * HH + cta * 4 + fhcl] = hv;
        }
    }
}

extern "C" void kernel_launch(void* const* d_in, const int* in_sizes, int n_in,
                              void* d_out, int out_size) {
    const float* x    = (const float*)d_in[0];
    const float* W_ih = (const float*)d_in[1];
    const float* W_hh = (const float*)d_in[2];
    const float* b_ih = (const float*)d_in[3];
    const float* b_hh = (const float*)d_in[4];
    float* out = (float*)d_out;

    const int p1_smem = BB * XS_STRIDE * 8 + 3 * 128 * WST * 8;            // 188,416
    const int p2_smem = (KPT * WST + NBUF * KPC * AST) * 8 + 2 * 16 * BB * 4; // 186,368
    cudaFuncSetAttribute(xgate_kernel,
                         cudaFuncAttributeMaxDynamicSharedMemorySize, p1_smem);
    cudaFuncSetAttribute(lstm_kernel,
                         cudaFuncAttributeMaxDynamicSharedMemorySize, p2_smem);

    xgate_kernel<<<dim3(16, TT), P1_THREADS, p1_smem>>>(x, W_ih, b_ih, b_hh);
    lstm_kernel<<<P2_GRID, P2_THREADS, p2_smem>>>(W_hh, out);
}

// round 10
// speedup vs baseline: 1.3434x; 1.3434x over previous
#include <cuda_runtime.h>
#include <cuda_bf16.h>
#include <cstdint>
#include <math.h>

// Problem dims
#define BB   128
#define TT   1024
#define II   256
#define HH   512
#define G4H  2048

// Phase 2 (mma.sync) config
#define P2_GRID    128
#define P2_THREADS 256   // 8 warps, each owns m16 of the 128-batch M dim
#define KC2  64          // k per cp.async chunk
#define NCH2 8           // chunks per step (8*64 = 512)
#define NROW 16          // gate rows per CTA (4 h-cols x 4 gates)

// Phase-2 smem byte offsets
#define WROW 1040                         // W row stride bytes (512*2 + 16 pad)
#define SM_W    0                         // [2 split][16 n][1040]   = 33,280
#define AROW 144                          // A row stride bytes (64*2 + 16 pad)
#define SM_A    33280                     // [4 buf][2 split][128 m][144] = 147,456
#define ABUF (2 * 128 * AROW)             // 36,864 per ring buffer
#define SM_XG   (SM_A + 4 * ABUF)         // 180,736: [2][16 r][128 b] f32 = 16,384
#define SM_DST  (SM_XG + 16384)           // 197,120: [128 m][18] f32 = 9,216
#define SM_TOTAL2 (SM_DST + 9216)         // 206,336

// Phase 1 config (R8, unchanged)
#define P1_THREADS 512
#define P1_KPCH 16
#define P1_NCH  (II / 2 / P1_KPCH)
#define XS_STRIDE 130
#define WST 18

typedef unsigned long long ull;

// Scratch
__device__ float g_xg[(size_t)TT * G4H * BB];   // [t][prow][b] x-gates + biases
__device__ __nv_bfloat16 g_h_hi[2][BB * HH];    // [buf][b][k] h high split
__device__ __nv_bfloat16 g_h_lo[2][BB * HH];    // [buf][b][k] h low split
__device__ unsigned g_bar_count;
__device__ unsigned g_bar_gen;

// ---------- packed fp32 helpers (phase 1) ----------
__device__ __forceinline__ void fma2(ull &d, ull a, ull b) {
    asm("fma.rn.f32x2 %0, %1, %2, %0;" : "+l"(d) : "l"(a), "l"(b));
}
__device__ __forceinline__ ull pack2(float lo, float hi) {
    ull r; asm("mov.b64 %0, {%1, %2};" : "=l"(r) : "f"(lo), "f"(hi)); return r;
}
__device__ __forceinline__ void unpack2(float &lo, float &hi, ull v) {
    asm("mov.b64 {%0, %1}, %2;" : "=f"(lo), "=f"(hi) : "l"(v));
}
// ---------- cp.async ----------
__device__ __forceinline__ void cp_async16(void* dst_smem, const void* src) {
    unsigned d = (unsigned)__cvta_generic_to_shared(dst_smem);
    asm volatile("cp.async.cg.shared.global [%0], [%1], 16;" :: "r"(d), "l"(src));
}
__device__ __forceinline__ void cp_commit() { asm volatile("cp.async.commit_group;"); }
template<int N> __device__ __forceinline__ void cp_wait() {
    asm volatile("cp.async.wait_group %0;" :: "n"(N));
}
__device__ __forceinline__ float sigf(float x) { return 1.0f / (1.0f + expf(-x)); }

__device__ __forceinline__ int prow_to_n(int prow) {
    int c2 = prow >> 4, r = prow & 15;
    return (r & 3) * HH + c2 * 4 + (r >> 2);
}
__device__ __forceinline__ uint32_t smem_u32(const void* p) {
    uint32_t a;
    asm("{ .reg .u64 t; cvta.to.shared.u64 t, %1; cvt.u32.u64 %0, t; }"
        : "=r"(a) : "l"(p));
    return a;
}
// ---------- mma.sync / ldmatrix (baseline PTX, sm_80+) ----------
__device__ __forceinline__ void ldsm4(uint32_t* r, uint32_t a) {
    asm volatile("ldmatrix.sync.aligned.m8n8.x4.shared.b16 {%0,%1,%2,%3}, [%4];"
        : "=r"(r[0]), "=r"(r[1]), "=r"(r[2]), "=r"(r[3]) : "r"(a));
}
__device__ __forceinline__ void mma_bf16(float* d, const uint32_t* a, const uint32_t* b) {
    asm volatile(
        "mma.sync.aligned.m16n8k16.row.col.f32.bf16.bf16.f32 "
        "{%0,%1,%2,%3}, {%4,%5,%6,%7}, {%8,%9}, {%0,%1,%2,%3};"
        : "+f"(d[0]), "+f"(d[1]), "+f"(d[2]), "+f"(d[3])
        : "r"(a[0]), "r"(a[1]), "r"(a[2]), "r"(a[3]), "r"(b[0]), "r"(b[1]));
}

// ---------- grid-wide barrier (monotonic count) ----------
__device__ __forceinline__ void grid_barrier(unsigned target) {
    __syncthreads();
    __threadfence();
    if (threadIdx.x == 0) {
        unsigned a = atomicAdd(&g_bar_count, 1u) + 1u;
        if (a == (unsigned)P2_GRID * target) {
            __threadfence();
            atomicAdd(&g_bar_gen, 1u);
        } else {
            while (*(volatile unsigned*)&g_bar_gen < target) { }
        }
        __threadfence();
    }
    __syncthreads();
}

// ============================================================================
// Phase 1 (R8): xg[t][prow][b] = x.W_ih^T + b_ih + b_hh
// ============================================================================
__global__ void __launch_bounds__(P1_THREADS, 1) xgate_kernel(
    const float* __restrict__ x, const float* __restrict__ W_ih,
    const float* __restrict__ b_ih, const float* __restrict__ b_hh)
{
    extern __shared__ char smem[];
    ull*   xs2   = (ull*)smem;
    float* s_out = (float*)smem;
    ull*   wbuf  = (ull*)(smem + BB * XS_STRIDE * 8);

    const int tid = threadIdx.x;
    const int gy  = blockIdx.x;
    const int t   = blockIdx.y;

    if (gy == 0 && t == 0 && tid == 0) { g_bar_count = 0u; g_bar_gen = 0u; }

    for (int e = tid; e < BB * (II / 4); e += P1_THREADS) {
        int b = e >> 6, v = e & 63;
        float4 f = *(const float4*)(x + ((size_t)b * TT + t) * II + 4 * v);
        ulonglong2 u;
        u.x = pack2(f.x, f.y);
        u.y = pack2(f.z, f.w);
        *(ulonglong2*)&xs2[b * XS_STRIDE + 2 * v] = u;
    }

    auto load_w = [&](int c) {
        ull* dst = wbuf + (c % 3) * (128 * WST);
        #pragma unroll
        for (int j = 0; j < 2; j++) {
            int u = tid + j * P1_THREADS;
            int row = u >> 3, kq = u & 7;
            int n = prow_to_n(gy * 128 + row);
            cp_async16(dst + row * WST + kq * 2,
                       W_ih + (size_t)n * II + c * (P1_KPCH * 2) + kq * 4);
        }
    };
    load_w(0); cp_commit();
    load_w(1); cp_commit();
    __syncthreads();

    const int rs   = tid >> 3;
    const int boct = tid & 7;
    const int p0   = gy * 128 + rs * 2;
    const int n0 = prow_to_n(p0), n1 = prow_to_n(p0 + 1);
    const float bias0 = b_ih[n0] + b_hh[n0];
    const float bias1 = b_ih[n1] + b_hh[n1];

    ull acc0[16], acc1[16];
    #pragma unroll
    for (int bb = 0; bb < 16; bb++) {
        acc0[bb] = pack2(bias0, 0.f);
        acc1[bb] = pack2(bias1, 0.f);
    }

    #pragma unroll 1
    for (int c = 0; c < P1_NCH; c++) {
        cp_wait<1>();
        __syncthreads();
        if (c + 2 < P1_NCH) { load_w(c + 2); cp_commit(); }
        else                { cp_commit(); }

        const ull* wb = wbuf + (c % 3) * (128 * WST);
        const ull* w0p = wb + (rs * 2) * WST;
        const ull* w1p = wb + (rs * 2 + 1) * WST;
        #pragma unroll 4
        for (int kpl = 0; kpl < P1_KPCH; kpl++) {
            ull w0 = w0p[kpl];
            ull w1 = w1p[kpl];
            const ull* ab = xs2 + c * P1_KPCH + kpl;
            #pragma unroll
            for (int bb = 0; bb < 16; bb++) {
                ull a = ab[(boct + 8 * bb) * XS_STRIDE];
                fma2(acc0[bb], a, w0);
                fma2(acc1[bb], a, w1);
            }
        }
    }
    __syncthreads();

    #pragma unroll
    for (int bb = 0; bb < 16; bb++) {
        float lo, hi;
        unpack2(lo, hi, acc0[bb]);
        s_out[(rs * 2 + 0) * 129 + boct + 8 * bb] = lo + hi;
        unpack2(lo, hi, acc1[bb]);
        s_out[(rs * 2 + 1) * 129 + boct + 8 * bb] = lo + hi;
    }
    __syncthreads();

    float* dst = g_xg + ((size_t)t * G4H + gy * 128) * BB;
    for (int e = tid; e < 128 * 128; e += P1_THREADS) {
        int row = e >> 7, b = e & 127;
        dst[e] = s_out[row * 129 + b];
    }
}

// ---------- phase-2 A-chunk loader: h splits -> padded row-major tiles ----------
__device__ __forceinline__ void load_A(char* smem, int ci, int hb, int tid) {
    char* base = smem + SM_A + (ci & 3) * ABUF;
    #pragma unroll
    for (int j = 0; j < 8; j++) {
        int e = tid + j * P2_THREADS;     // 0..2047 16B units
        int split = e >> 10;              // 0: hi, 1: lo
        int r = e & 1023;
        int m = r >> 3;                   // batch 0..127
        int u = r & 7;                    // 16B unit within 128B of k64
        const __nv_bfloat16* src =
            (split ? g_h_lo[hb] : g_h_hi[hb]) + (size_t)m * HH + ci * KC2 + u * 8;
        cp_async16(base + split * (128 * AROW) + m * AROW + u * 16, src);
    }
}

// ============================================================================
// Phase 2: persistent mma.sync recurrence. 128 CTAs x 256 thr (8 warps).
// Per CTA/step: D[128 b x 16 rows] = h @ W_hh^T via 3xBF16 (hi/lo splits).
// Warp w owns batches 16w..16w+15; accumulators in registers — no MMA barrier.
// ============================================================================
__global__ void __launch_bounds__(P2_THREADS, 1) lstm_kernel(
    const float* __restrict__ W_hh, float* __restrict__ out)
{
    extern __shared__ char smem[];
    const uint32_t sb = smem_u32(smem);
    const int tid = threadIdx.x;
    const int w = tid >> 5, l = tid & 31;
    const int cta = blockIdx.x;

    // W_hh -> bf16 hi/lo tiles [split][n 16][1040B rows], once
    for (int idx = tid; idx < NROW * HH; idx += P2_THREADS) {
        int r = idx >> 9;                 // local row: r = hc*4 + gate
        int k = idx & 511;
        int n = (r & 3) * HH + cta * 4 + (r >> 2);
        float v = W_hh[(size_t)n * HH + k];
        __nv_bfloat16 hi = __float2bfloat16(v);
        __nv_bfloat16 lo = __float2bfloat16(v - __bfloat162float(hi));
        *(__nv_bfloat16*)(smem + SM_W + r * WROW + k * 2)                = hi;
        *(__nv_bfloat16*)(smem + SM_W + NROW * WROW + r * WROW + k * 2)  = lo;
    }
    // Zero h buf0 own slice (4 cols x 128 b, both splits)
    {
        int b = tid & 127, hcp = tid >> 7;   // hcp 0..1 -> h-col pair
        __nv_bfloat162 z; z.x = __float2bfloat16(0.f); z.y = z.x;
        *(__nv_bfloat162*)&g_h_hi[0][(size_t)b * HH + cta * 4 + 2 * hcp] = z;
        *(__nv_bfloat162*)&g_h_lo[0][(size_t)b * HH + cta * 4 + 2 * hcp] = z;
    }
    // Prefetch xg(0): 16 rows x 128 b f32 = 8 KB
    {
        const char* src = (const char*)(g_xg + ((size_t)cta * NROW) * BB);
        cp_async16(smem + SM_XG + tid * 16, src + tid * 16);
        cp_async16(smem + SM_XG + (tid + 256) * 16, src + (tid + 256) * 16);
        cp_commit();
    }

    // ldmatrix lane addressing (fixed per thread)
    const int lm = l & 15, kh = l >> 4;            // A: row m, k-half
    const int brow = (l & 7) + ((l >> 4) << 3);    // B: n row
    const int bhalf = (l >> 3) & 1;                // B: k-half
    const uint32_t aoff = (uint32_t)((16 * w + lm) * AROW + kh * 16);
    const uint32_t boff = (uint32_t)(brow * WROW + bhalf * 16);

    float cs[2] = {0.f, 0.f};
    unsigned gen = 0;
    grid_barrier(++gen);

    for (int t = 0; t < TT; t++) {
        const int hb = t & 1;
        load_A(smem, 0, hb, tid); cp_commit();
        load_A(smem, 1, hb, tid); cp_commit();

        float d0[4] = {0.f, 0.f, 0.f, 0.f};   // n0-7
        float d1[4] = {0.f, 0.f, 0.f, 0.f};   // n8-15

        #pragma unroll 1
        for (int ci = 0; ci < NCH2; ci++) {
            if (ci < NCH2 - 2) {
                load_A(smem, ci + 2, hb, tid);
                cp_commit();
            } else if (ci == NCH2 - 2) {
                if (t + 1 < TT) {
                    const char* src =
                        (const char*)(g_xg + ((size_t)(t + 1) * G4H + cta * NROW) * BB);
                    char* d = smem + SM_XG + ((t + 1) & 1) * 8192;
                    cp_async16(d + tid * 16, src + tid * 16);
                    cp_async16(d + (tid + 256) * 16, src + (tid + 256) * 16);
                }
                cp_commit();
            } else {
                cp_commit();
            }
            cp_wait<2>();
            __syncthreads();   // chunk ci visible to all warps

            const uint32_t Ab = sb + SM_A + (ci & 3) * ABUF + aoff;
            const uint32_t Bb = sb + SM_W + boff + ci * 128;   // k byte offset
            #pragma unroll
            for (int ks = 0; ks < 4; ks++) {
                uint32_t ah[4], al[4], bh[4], bl[4];
                ldsm4(ah, Ab + ks * 32);
                ldsm4(al, Ab + 128 * AROW + ks * 32);
                ldsm4(bh, Bb + ks * 32);
                ldsm4(bl, Bb + NROW * WROW + ks * 32);
                mma_bf16(d0, ah, bh);
                mma_bf16(d1, ah, bh + 2);
                mma_bf16(d0, al, bh);
                mma_bf16(d1, al, bh + 2);
                mma_bf16(d0, ah, bl);
                mma_bf16(d1, ah, bl + 2);
            }
        }

        // ---- stage D to smem, then activations ----
        {
            float* Ds = (float*)(smem + SM_DST);
            int m0 = 16 * w + (l >> 2);
            int c0 = 2 * (l & 3);
            *(float2*)&Ds[m0 * 18 + c0]           = make_float2(d0[0], d0[1]);
            *(float2*)&Ds[(m0 + 8) * 18 + c0]     = make_float2(d0[2], d0[3]);
            *(float2*)&Ds[m0 * 18 + c0 + 8]       = make_float2(d1[0], d1[1]);
            *(float2*)&Ds[(m0 + 8) * 18 + c0 + 8] = make_float2(d1[2], d1[3]);
        }
        __syncthreads();

        {
            const float* Ds = (const float*)(smem + SM_DST);
            const float* xg = (const float*)(smem + SM_XG + (t & 1) * 8192);
            const int b = tid & 127, hcp = tid >> 7;
            float hv[2];
            #pragma unroll
            for (int j = 0; j < 2; j++) {
                int r0 = (2 * hcp + j) * 4;
                float gi = Ds[b * 18 + r0 + 0] + xg[(r0 + 0) * BB + b];
                float gf = Ds[b * 18 + r0 + 1] + xg[(r0 + 1) * BB + b];
                float gg = Ds[b * 18 + r0 + 2] + xg[(r0 + 2) * BB + b];
                float go = Ds[b * 18 + r0 + 3] + xg[(r0 + 3) * BB + b];
                float ig = sigf(gi), fg = sigf(gf), g2 = tanhf(gg), og = sigf(go);
                cs[j] = fg * cs[j] + ig * g2;
                hv[j] = og * tanhf(cs[j]);
            }
            if (t < TT - 1) {
                __nv_bfloat16 h0 = __float2bfloat16(hv[0]);
                __nv_bfloat16 h1 = __float2bfloat16(hv[1]);
                __nv_bfloat16 l0 = __float2bfloat16(hv[0] - __bfloat162float(h0));
                __nv_bfloat16 l1 = __float2bfloat16(hv[1] - __bfloat162float(h1));
                __nv_bfloat162 ph; ph.x = h0; ph.y = h1;
                __nv_bfloat162 pl; pl.x = l0; pl.y = l1;
                size_t off = (size_t)b * HH + cta * 4 + 2 * hcp;
                *(__nv_bfloat162*)&g_h_hi[(t + 1) & 1][off] = ph;
                *(__nv_bfloat162*)&g_h_lo[(t + 1) & 1][off] = pl;
            } else {
                *(float2*)(out + (size_t)b * HH + cta * 4 + 2 * hcp) =
                    make_float2(hv[0], hv[1]);
            }
        }
        if (t < TT - 1) grid_barrier(++gen);
    }
}

extern "C" void kernel_launch(void* const* d_in, const int* in_sizes, int n_in,
                              void* d_out, int out_size) {
    const float* x    = (const float*)d_in[0];
    const float* W_ih = (const float*)d_in[1];
    const float* W_hh = (const float*)d_in[2];
    const float* b_ih = (const float*)d_in[3];
    const float* b_hh = (const float*)d_in[4];
    float* out = (float*)d_out;

    const int p1_smem = BB * XS_STRIDE * 8 + 3 * 128 * WST * 8;   // 188,416
    cudaFuncSetAttribute(xgate_kernel,
                         cudaFuncAttributeMaxDynamicSharedMemorySize, p1_smem);
    cudaFuncSetAttribute(lstm_kernel,
                         cudaFuncAttributeMaxDynamicSharedMemorySize, SM_TOTAL2);

    xgate_kernel<<<dim3(16, TT), P1_THREADS, p1_smem>>>(x, W_ih, b_ih, b_hh);
    lstm_kernel<<<P2_GRID, P2_THREADS, SM_TOTAL2>>>(W_hh, out);
}

// round 11
// speedup vs baseline: 1.9637x; 1.4617x over previous
#include <cuda_runtime.h>
#include <cuda_bf16.h>
#include <cstdint>
#include <math.h>

// Problem dims
#define BB   128
#define TT   1024
#define II   256
#define HH   512
#define G4H  2048

// ---------------- Phase 2 (lstm mma.sync) config ----------------
#define P2_GRID    128
#define P2_THREADS 256
#define KC2  64
#define NCH2 8
#define NROW 16
#define WROW 1040                         // W_hh row stride bytes
#define SM_W    0                         // [2 split][16 n][1040] = 33,280
#define AROW 144                          // A row stride bytes
#define SM_A    33280                     // [4 buf][2 split][128 m][144]
#define ABUF (2 * 128 * AROW)             // 36,864
#define SM_XG   (SM_A + 4 * ABUF)         // 180,736: [2][16 r][128 b] f32
#define SM_DST  (SM_XG + 16384)           // 197,120: [128 m][18] f32
#define SM_TOTAL2 (SM_DST + 9216)         // 206,336

// ---------------- Phase 1 (xgate mma.sync) config ----------------
#define G1_THREADS 256
#define WROW1 528                          // W_ih row stride bytes (256*2+16)
#define SM1_W    0                         // [2 split][64 n][528] = 67,584
#define SM1_A    67584                     // [4 buf][2 split][128 m][144]
#define SM1_BIAS (SM1_A + 4 * ABUF)        // 215,040 (+256)
#define SM_TOTAL1 (SM1_BIAS + 256)         // 215,296

typedef unsigned long long ull;

// Scratch
__device__ float g_xg[(size_t)TT * G4H * BB];     // [t][prow][b] x-gates + biases
__device__ __nv_bfloat16 g_h_hi[2][BB * HH];      // [buf][b][k]
__device__ __nv_bfloat16 g_h_lo[2][BB * HH];
__device__ __nv_bfloat16 g_x_hi[(size_t)TT * BB * II];  // [t][b][i]
__device__ __nv_bfloat16 g_x_lo[(size_t)TT * BB * II];
__device__ __nv_bfloat16 g_wih_hi[G4H * II];      // [prow][i]
__device__ __nv_bfloat16 g_wih_lo[G4H * II];
__device__ unsigned g_bar_count;
__device__ unsigned g_bar_gen;

// ---------- cp.async ----------
__device__ __forceinline__ void cp_async16(void* dst_smem, const void* src) {
    unsigned d = (unsigned)__cvta_generic_to_shared(dst_smem);
    asm volatile("cp.async.cg.shared.global [%0], [%1], 16;" :: "r"(d), "l"(src));
}
__device__ __forceinline__ void cp_commit() { asm volatile("cp.async.commit_group;"); }
template<int N> __device__ __forceinline__ void cp_wait() {
    asm volatile("cp.async.wait_group %0;" :: "n"(N));
}
__device__ __forceinline__ float sigf(float x) { return 1.0f / (1.0f + expf(-x)); }

__device__ __forceinline__ int prow_to_n(int prow) {
    int c2 = prow >> 4, r = prow & 15;
    return (r & 3) * HH + c2 * 4 + (r >> 2);
}
__device__ __forceinline__ uint32_t smem_u32(const void* p) {
    uint32_t a;
    asm("{ .reg .u64 t; cvta.to.shared.u64 t, %1; cvt.u32.u64 %0, t; }"
        : "=r"(a) : "l"(p));
    return a;
}
// ---------- mma.sync / ldmatrix (baseline PTX) ----------
__device__ __forceinline__ void ldsm4(uint32_t* r, uint32_t a) {
    asm volatile("ldmatrix.sync.aligned.m8n8.x4.shared.b16 {%0,%1,%2,%3}, [%4];"
        : "=r"(r[0]), "=r"(r[1]), "=r"(r[2]), "=r"(r[3]) : "r"(a));
}
__device__ __forceinline__ void mma_bf16(float* d, const uint32_t* a, const uint32_t* b) {
    asm volatile(
        "mma.sync.aligned.m16n8k16.row.col.f32.bf16.bf16.f32 "
        "{%0,%1,%2,%3}, {%4,%5,%6,%7}, {%8,%9}, {%0,%1,%2,%3};"
        : "+f"(d[0]), "+f"(d[1]), "+f"(d[2]), "+f"(d[3])
        : "r"(a[0]), "r"(a[1]), "r"(a[2]), "r"(a[3]), "r"(b[0]), "r"(b[1]));
}

// ---------- grid-wide barrier (monotonic count) ----------
__device__ __forceinline__ void grid_barrier(unsigned target) {
    __syncthreads();
    __threadfence();
    if (threadIdx.x == 0) {
        unsigned a = atomicAdd(&g_bar_count, 1u) + 1u;
        if (a == (unsigned)P2_GRID * target) {
            __threadfence();
            atomicAdd(&g_bar_gen, 1u);
        } else {
            while (*(volatile unsigned*)&g_bar_gen < target) { }
        }
        __threadfence();
    }
    __syncthreads();
}

// ============================================================================
// Prep: split x -> [t][b][i] bf16 hi/lo, W_ih -> [prow][i] bf16 hi/lo,
// reset barrier. DRAM-bound, ~0.15 ms.
// ============================================================================
__global__ void __launch_bounds__(256, 1) prep_kernel(
    const float* __restrict__ x, const float* __restrict__ W_ih)
{
    const int bl = blockIdx.x;   // 8192
    const int tid = threadIdx.x; // i index (II == 256)
    if (bl == 0 && tid == 0) { g_bar_count = 0u; g_bar_gen = 0u; }

    #pragma unroll 4
    for (int it = 0; it < 16; it++) {
        int row = bl * 16 + it;          // row = b*T + t
        int b = row >> 10, t = row & 1023;
        float v = x[(size_t)row * II + tid];
        __nv_bfloat16 hi = __float2bfloat16(v);
        __nv_bfloat16 lo = __float2bfloat16(v - __bfloat162float(hi));
        size_t o = ((size_t)t * BB + b) * II + tid;
        g_x_hi[o] = hi;
        g_x_lo[o] = lo;
    }
    if (bl < G4H) {
        int n = prow_to_n(bl);
        float v = W_ih[(size_t)n * II + tid];
        __nv_bfloat16 hi = __float2bfloat16(v);
        __nv_bfloat16 lo = __float2bfloat16(v - __bfloat162float(hi));
        g_wih_hi[bl * II + tid] = hi;
        g_wih_lo[bl * II + tid] = lo;
    }
}

// ============================================================================
// Phase 1: xg[t][prow][b] = x_t . W_ih^T + biases via 3xBF16 mma.sync.
// Grid (32 rowgroups of 64, 1024 t) x 256 thr. Per CTA: M=128 N=64 K=256.
// Warp w owns m16 batch rows; per-warp A loads, ring-4 cp.async.
// ============================================================================
__global__ void __launch_bounds__(G1_THREADS, 1) xgate_kernel(
    const float* __restrict__ b_ih, const float* __restrict__ b_hh)
{
    extern __shared__ char smem[];
    const uint32_t sb = smem_u32(smem);
    const int tid = threadIdx.x;
    const int w = tid >> 5, l = tid & 31;
    const int gy = blockIdx.x;   // rowgroup: prows gy*64..+63
    const int t  = blockIdx.y;

    // W tile: [split][64 r][528B] from pre-split gmem (group 1)
    #pragma unroll
    for (int j = 0; j < 16; j++) {
        int e = tid + j * G1_THREADS;   // 0..4095 units
        int split = e >> 11, r = (e >> 5) & 63, u = e & 31;
        const __nv_bfloat16* src =
            (split ? g_wih_lo : g_wih_hi) + (size_t)(gy * 64 + r) * II + u * 8;
        cp_async16(smem + SM1_W + split * (64 * WROW1) + r * WROW1 + u * 16, src);
    }
    cp_commit();

    // per-warp A chunk loader: warp w's rows 16w..16w+15, chunk ci (64 k)
    auto load_A = [&](int ci) {
        char* base = smem + SM1_A + (ci & 3) * ABUF;
        #pragma unroll
        for (int j = 0; j < 8; j++) {
            int e = l + j * 32;          // 0..255
            int split = e >> 7, m16 = (e >> 3) & 15, u = e & 7;
            int m = 16 * w + m16;
            const __nv_bfloat16* src =
                (split ? g_x_lo : g_x_hi) +
                ((size_t)t * BB + m) * II + ci * KC2 + u * 8;
            cp_async16(base + split * (128 * AROW) + m * AROW + u * 16, src);
        }
    };
    load_A(0); cp_commit();
    load_A(1); cp_commit();

    if (tid < 64) {
        int n = prow_to_n(gy * 64 + tid);
        ((float*)(smem + SM1_BIAS))[tid] = b_ih[n] + b_hh[n];
    }

    const int lm = l & 15, kh = l >> 4;
    const int brow = (l & 7) + ((l >> 4) << 3);
    const int bhalf = (l >> 3) & 1;
    const uint32_t aoff = (uint32_t)((16 * w + lm) * AROW + kh * 16);
    const uint32_t boff = (uint32_t)(brow * WROW1 + bhalf * 16);

    float d[8][4];
    #pragma unroll
    for (int i = 0; i < 8; i++)
        #pragma unroll
        for (int q = 0; q < 4; q++) d[i][q] = 0.f;

    #pragma unroll 1
    for (int ci = 0; ci < 4; ci++) {
        if (ci < 2) { load_A(ci + 2); cp_commit(); }
        else        { cp_commit(); }
        cp_wait<2>();
        if (ci == 0) __syncthreads();   // W + A0 visible block-wide
        else         __syncwarp();

        const uint32_t Ab = sb + SM1_A + (ci & 3) * ABUF + aoff;
        const uint32_t Bb = sb + SM1_W + boff + ci * 128;
        #pragma unroll
        for (int ks = 0; ks < 4; ks++) {
            uint32_t ah[4], al[4];
            ldsm4(ah, Ab + ks * 32);
            ldsm4(al, Ab + 128 * AROW + ks * 32);
            #pragma unroll
            for (int g = 0; g < 4; g++) {
                uint32_t bh[4], bl[4];
                ldsm4(bh, Bb + g * 16 * WROW1 + ks * 32);
                ldsm4(bl, Bb + 64 * WROW1 + g * 16 * WROW1 + ks * 32);
                mma_bf16(d[2 * g],     ah, bh);
                mma_bf16(d[2 * g + 1], ah, bh + 2);
                mma_bf16(d[2 * g],     al, bh);
                mma_bf16(d[2 * g + 1], al, bh + 2);
                mma_bf16(d[2 * g],     ah, bl);
                mma_bf16(d[2 * g + 1], ah, bl + 2);
            }
        }
    }
    __syncthreads();   // all ring reads done -> reuse buf0 as D stage

    {
        float* Ds = (float*)(smem + SM1_A);   // [128 m][72]
        int m0 = 16 * w + (l >> 2);
        int c0 = 2 * (l & 3);
        #pragma unroll
        for (int g = 0; g < 4; g++) {
            *(float2*)&Ds[m0 * 72 + 16 * g + c0]           = make_float2(d[2*g][0], d[2*g][1]);
            *(float2*)&Ds[(m0 + 8) * 72 + 16 * g + c0]     = make_float2(d[2*g][2], d[2*g][3]);
            *(float2*)&Ds[m0 * 72 + 16 * g + 8 + c0]       = make_float2(d[2*g+1][0], d[2*g+1][1]);
            *(float2*)&Ds[(m0 + 8) * 72 + 16 * g + 8 + c0] = make_float2(d[2*g+1][2], d[2*g+1][3]);
        }
    }
    __syncthreads();

    {
        const float* Ds = (const float*)(smem + SM1_A);
        const float* bias_s = (const float*)(smem + SM1_BIAS);
        float* dst = g_xg + ((size_t)t * G4H + gy * 64) * BB;
        #pragma unroll 4
        for (int it = 0; it < 32; it++) {
            int e = it * G1_THREADS + tid;   // 0..8191
            int r = e >> 7, b = e & 127;
            dst[e] = Ds[b * 72 + r] + bias_s[r];
        }
    }
}

// ============================================================================
// Phase 2: persistent mma.sync recurrence (R10), per-warp A loads, no
// per-chunk block syncs.
// ============================================================================
__global__ void __launch_bounds__(P2_THREADS, 1) lstm_kernel(
    const float* __restrict__ W_hh, float* __restrict__ out)
{
    extern __shared__ char smem[];
    const uint32_t sb = smem_u32(smem);
    const int tid = threadIdx.x;
    const int w = tid >> 5, l = tid & 31;
    const int cta = blockIdx.x;

    // W_hh -> bf16 hi/lo tiles, once
    for (int idx = tid; idx < NROW * HH; idx += P2_THREADS) {
        int r = idx >> 9;
        int k = idx & 511;
        int n = (r & 3) * HH + cta * 4 + (r >> 2);
        float v = W_hh[(size_t)n * HH + k];
        __nv_bfloat16 hi = __float2bfloat16(v);
        __nv_bfloat16 lo = __float2bfloat16(v - __bfloat162float(hi));
        *(__nv_bfloat16*)(smem + SM_W + r * WROW + k * 2)               = hi;
        *(__nv_bfloat16*)(smem + SM_W + NROW * WROW + r * WROW + k * 2) = lo;
    }
    {
        int b = tid & 127, hcp = tid >> 7;
        __nv_bfloat162 z; z.x = __float2bfloat16(0.f); z.y = z.x;
        *(__nv_bfloat162*)&g_h_hi[0][(size_t)b * HH + cta * 4 + 2 * hcp] = z;
        *(__nv_bfloat162*)&g_h_lo[0][(size_t)b * HH + cta * 4 + 2 * hcp] = z;
    }
    {
        const char* src = (const char*)(g_xg + ((size_t)cta * NROW) * BB);
        cp_async16(smem + SM_XG + tid * 16, src + tid * 16);
        cp_async16(smem + SM_XG + (tid + 256) * 16, src + (tid + 256) * 16);
        cp_commit();
    }

    // per-warp A chunk loader: warp w's rows 16w..16w+15
    auto load_A = [&](int ci, int hb) {
        char* base = smem + SM_A + (ci & 3) * ABUF;
        #pragma unroll
        for (int j = 0; j < 8; j++) {
            int e = l + j * 32;
            int split = e >> 7, m16 = (e >> 3) & 15, u = e & 7;
            int m = 16 * w + m16;
            const __nv_bfloat16* src =
                (split ? g_h_lo[hb] : g_h_hi[hb]) + (size_t)m * HH + ci * KC2 + u * 8;
            cp_async16(base + split * (128 * AROW) + m * AROW + u * 16, src);
        }
    };

    const int lm = l & 15, kh = l >> 4;
    const int brow = (l & 7) + ((l >> 4) << 3);
    const int bhalf = (l >> 3) & 1;
    const uint32_t aoff = (uint32_t)((16 * w + lm) * AROW + kh * 16);
    const uint32_t boff = (uint32_t)(brow * WROW + bhalf * 16);

    float cs[2] = {0.f, 0.f};
    unsigned gen = 0;
    grid_barrier(++gen);   // W tiles + h0 + xg prefetch ordering

    for (int t = 0; t < TT; t++) {
        const int hb = t & 1;
        load_A(0, hb); cp_commit();
        load_A(1, hb); cp_commit();

        float d0[4] = {0.f, 0.f, 0.f, 0.f};
        float d1[4] = {0.f, 0.f, 0.f, 0.f};

        #pragma unroll 1
        for (int ci = 0; ci < NCH2; ci++) {
            if (ci < NCH2 - 2) {
                load_A(ci + 2, hb);
                cp_commit();
            } else if (ci == NCH2 - 2) {
                if (t + 1 < TT) {
                    const char* src =
                        (const char*)(g_xg + ((size_t)(t + 1) * G4H + cta * NROW) * BB);
                    char* dd = smem + SM_XG + ((t + 1) & 1) * 8192;
                    cp_async16(dd + tid * 16, src + tid * 16);
                    cp_async16(dd + (tid + 256) * 16, src + (tid + 256) * 16);
                }
                cp_commit();
            } else {
                cp_commit();
            }
            cp_wait<2>();
            __syncwarp();   // warp-local chunk readiness (warp loaded its own rows)

            const uint32_t Ab = sb + SM_A + (ci & 3) * ABUF + aoff;
            const uint32_t Bb = sb + SM_W + boff + ci * 128;
            #pragma unroll
            for (int ks = 0; ks < 4; ks++) {
                uint32_t ah[4], al[4], bh[4], bl[4];
                ldsm4(ah, Ab + ks * 32);
                ldsm4(al, Ab + 128 * AROW + ks * 32);
                ldsm4(bh, Bb + ks * 32);
                ldsm4(bl, Bb + NROW * WROW + ks * 32);
                mma_bf16(d0, ah, bh);
                mma_bf16(d1, ah, bh + 2);
                mma_bf16(d0, al, bh);
                mma_bf16(d1, al, bh + 2);
                mma_bf16(d0, ah, bl);
                mma_bf16(d1, ah, bl + 2);
            }
        }

        {
            float* Ds = (float*)(smem + SM_DST);
            int m0 = 16 * w + (l >> 2);
            int c0 = 2 * (l & 3);
            *(float2*)&Ds[m0 * 18 + c0]           = make_float2(d0[0], d0[1]);
            *(float2*)&Ds[(m0 + 8) * 18 + c0]     = make_float2(d0[2], d0[3]);
            *(float2*)&Ds[m0 * 18 + c0 + 8]       = make_float2(d1[0], d1[1]);
            *(float2*)&Ds[(m0 + 8) * 18 + c0 + 8] = make_float2(d1[2], d1[3]);
        }
        __syncthreads();   // D stage + (retired) xg visible block-wide

        {
            const float* Ds = (const float*)(smem + SM_DST);
            const float* xg = (const float*)(smem + SM_XG + (t & 1) * 8192);
            const int b = tid & 127, hcp = tid >> 7;
            float hv[2];
            #pragma unroll
            for (int j = 0; j < 2; j++) {
                int r0 = (2 * hcp + j) * 4;
                float gi = Ds[b * 18 + r0 + 0] + xg[(r0 + 0) * BB + b];
                float gf = Ds[b * 18 + r0 + 1] + xg[(r0 + 1) * BB + b];
                float gg = Ds[b * 18 + r0 + 2] + xg[(r0 + 2) * BB + b];
                float go = Ds[b * 18 + r0 + 3] + xg[(r0 + 3) * BB + b];
                float ig = sigf(gi), fg = sigf(gf), g2 = tanhf(gg), og = sigf(go);
                cs[j] = fg * cs[j] + ig * g2;
                hv[j] = og * tanhf(cs[j]);
            }
            if (t < TT - 1) {
                __nv_bfloat16 h0 = __float2bfloat16(hv[0]);
                __nv_bfloat16 h1 = __float2bfloat16(hv[1]);
                __nv_bfloat16 l0 = __float2bfloat16(hv[0] - __bfloat162float(h0));
                __nv_bfloat16 l1 = __float2bfloat16(hv[1] - __bfloat162float(h1));
                __nv_bfloat162 ph; ph.x = h0; ph.y = h1;
                __nv_bfloat162 pl; pl.x = l0; pl.y = l1;
                size_t off = (size_t)b * HH + cta * 4 + 2 * hcp;
                *(__nv_bfloat162*)&g_h_hi[(t + 1) & 1][off] = ph;
                *(__nv_bfloat162*)&g_h_lo[(t + 1) & 1][off] = pl;
            } else {
                *(float2*)(out + (size_t)b * HH + cta * 4 + 2 * hcp) =
                    make_float2(hv[0], hv[1]);
            }
        }
        if (t < TT - 1) grid_barrier(++gen);
    }
}

extern "C" void kernel_launch(void* const* d_in, const int* in_sizes, int n_in,
                              void* d_out, int out_size) {
    const float* x    = (const float*)d_in[0];
    const float* W_ih = (const float*)d_in[1];
    const float* W_hh = (const float*)d_in[2];
    const float* b_ih = (const float*)d_in[3];
    const float* b_hh = (const float*)d_in[4];
    float* out = (float*)d_out;

    cudaFuncSetAttribute(xgate_kernel,
                         cudaFuncAttributeMaxDynamicSharedMemorySize, SM_TOTAL1);
    cudaFuncSetAttribute(lstm_kernel,
                         cudaFuncAttributeMaxDynamicSharedMemorySize, SM_TOTAL2);

    prep_kernel<<<8192, 256>>>(x, W_ih);                                  // splits + barrier reset
    xgate_kernel<<<dim3(32, TT), G1_THREADS, SM_TOTAL1>>>(b_ih, b_hh);    // x-gates via mma
    lstm_kernel<<<P2_GRID, P2_THREADS, SM_TOTAL2>>>(W_hh, out);           // recurrence
}